// round 8
// baseline (speedup 1.0000x reference)
#include <cuda_runtime.h>
#include <math.h>
#include <stdint.h>
#include <stddef.h>

#define BDIM 128
#define TDIM 512
#define IDIM 32
#define HDIM 1024
#define GDIM 4096          // 4*H
#define BH   (BDIM*HDIM)
#define NBLK 128           // persistent grid: <=148 SMs -> all co-resident
#define NTHR 256

// ---------------- static device scratch (no allocations anywhere) ----------------
static __device__ float g_xg[(size_t)BDIM * TDIM * GDIM];    // hoisted input-gate preacts (1 GiB)
static __device__ float g_seqA[(size_t)BDIM * TDIM * HDIM];  // layer activations ping (256 MB)
static __device__ float g_seqB[(size_t)BDIM * TDIM * HDIM];  // layer activations pong (256 MB)
static __device__ float g_zero[BH];                          // never written -> stays 0
static __device__ float g_hbuf[2 * 3 * BH];                  // decoder h ping-pong; [0] = enc hT
static __device__ float g_cT[3 * BH];                        // encoder final c per layer
static __device__ float g_xfeed[BDIM];                       // decoder scalar feedback
static __device__ unsigned g_count = 0;                      // grid barrier
static __device__ unsigned g_gen = 0;

// ---------------- software grid barrier (all NBLK blocks resident) ----------------
__device__ __forceinline__ void gsync() {
    __syncthreads();
    if (threadIdx.x == 0) {
        unsigned gen = *((volatile unsigned*)&g_gen);
        __threadfence();
        if (atomicAdd(&g_count, 1u) == gridDim.x - 1) {
            atomicExch(&g_count, 0u);
            __threadfence();
            *((volatile unsigned*)&g_gen) = gen + 1u;
        } else {
            while (*((volatile unsigned*)&g_gen) == gen) __nanosleep(64);
        }
        __threadfence();
    }
    __syncthreads();
}

__device__ __forceinline__ float sigm(float x) { return 1.f / (1.f + expf(-x)); }

// dot4 as a function: avoids the macro-parameter / .w member-name collision.
__device__ __forceinline__ void dot4(float& ac, const float4 a, const float4 b) {
    ac += a.x * b.x; ac += a.y * b.y; ac += a.z * b.z; ac += a.w * b.w;
}

// ---------------- tile accumulator ----------------
// Adds A[128,1024] @ W^T (selected 32 rows) into acc[4][4].
// Block owns units u0..u0+7; thread (tx,ty): tx=unit offset, ty*4+i = batch row.
// acc[i][q] = sum_k A[4*ty+i][k] * W[q*1024 + u0 + tx][k]
__device__ __forceinline__ void accum_K(
    const float* __restrict__ A, size_t strideA,
    const float* __restrict__ W, int u0,
    float acc[4][4], float (*shA)[36], float (*shW)[36])
{
    const int tid = threadIdx.x;
    const int tx  = tid & 7;
    const int ty  = tid >> 3;
    const int kqo = (tid & 7) * 4;     // k-offset within 32-chunk (float4 granularity)
    const int b0  = tid >> 3;          // 0..31: A row group base / W row id

    const int wrow = ((b0 & 3) << 10) + u0 + (b0 >> 2);  // gate (b0&3), unit (b0>>2)
    const float* Wp = W + (size_t)wrow * HDIM + kqo;

    float4 ra[4], rw;
#pragma unroll
    for (int r = 0; r < 4; r++)
        ra[r] = *(const float4*)&A[(size_t)(b0 + 32 * r) * strideA + kqo];
    rw = *(const float4*)&Wp[0];

#pragma unroll 1
    for (int ch = 0; ch < 32; ch++) {
        __syncthreads();
#pragma unroll
        for (int r = 0; r < 4; r++)
            *(float4*)&shA[b0 + 32 * r][kqo] = ra[r];
        *(float4*)&shW[b0][kqo] = rw;
        __syncthreads();
        if (ch < 31) {
            const int k0 = (ch + 1) * 32;
#pragma unroll
            for (int r = 0; r < 4; r++)
                ra[r] = *(const float4*)&A[(size_t)(b0 + 32 * r) * strideA + k0 + kqo];
            rw = *(const float4*)&Wp[k0];
        }
#pragma unroll
        for (int k4 = 0; k4 < 8; k4++) {
            float4 a0 = *(const float4*)&shA[4 * ty + 0][4 * k4];
            float4 a1 = *(const float4*)&shA[4 * ty + 1][4 * k4];
            float4 a2 = *(const float4*)&shA[4 * ty + 2][4 * k4];
            float4 a3 = *(const float4*)&shA[4 * ty + 3][4 * k4];
            float4 w0 = *(const float4*)&shW[4 * tx + 0][4 * k4];
            float4 w1 = *(const float4*)&shW[4 * tx + 1][4 * k4];
            float4 w2 = *(const float4*)&shW[4 * tx + 2][4 * k4];
            float4 w3 = *(const float4*)&shW[4 * tx + 3][4 * k4];
            dot4(acc[0][0], a0, w0); dot4(acc[0][1], a0, w1); dot4(acc[0][2], a0, w2); dot4(acc[0][3], a0, w3);
            dot4(acc[1][0], a1, w0); dot4(acc[1][1], a1, w1); dot4(acc[1][2], a1, w2); dot4(acc[1][3], a1, w3);
            dot4(acc[2][0], a2, w0); dot4(acc[2][1], a2, w1); dot4(acc[2][2], a2, w2); dot4(acc[2][3], a2, w3);
            dot4(acc[3][0], a3, w0); dot4(acc[3][1], a3, w1); dot4(acc[3][2], a3, w2); dot4(acc[3][3], a3, w3);
        }
    }
}

// ---------------- persistent encoder layer ----------------
__global__ void __launch_bounds__(NTHR, 1) enc_layer_kernel(
    const float* __restrict__ Whh, const float* __restrict__ xg,
    const float* __restrict__ bih, const float* __restrict__ bhh,
    const float* __restrict__ zbuf,
    float* __restrict__ seq_out,     // [B,T,H]
    float* __restrict__ cT_out, float* __restrict__ hT_out)
{
    __shared__ float shA[128][36];
    __shared__ float shW[32][36];
    const int tid = threadIdx.x;
    const int tx = tid & 7, ty = tid >> 3;
    const int u0 = blockIdx.x * 8;
    const int u  = u0 + tx;

    float bs[4];
#pragma unroll
    for (int q = 0; q < 4; q++) bs[q] = bih[(q << 10) + u] + bhh[(q << 10) + u];

    float cl[4] = {0.f, 0.f, 0.f, 0.f};
    float hl[4] = {0.f, 0.f, 0.f, 0.f};

#pragma unroll 1
    for (int t = 0; t < TDIM; t++) {
        float acc[4][4];
#pragma unroll
        for (int i = 0; i < 4; i++)
#pragma unroll
            for (int j = 0; j < 4; j++) acc[i][j] = 0.f;

        const float* Ap = t ? (seq_out + (size_t)(t - 1) * HDIM) : zbuf;
        const size_t st = t ? (size_t)TDIM * HDIM : (size_t)HDIM;
        accum_K(Ap, st, Whh, u0, acc, shA, shW);

#pragma unroll
        for (int i = 0; i < 4; i++) {
            const int b = 4 * ty + i;
            const size_t xr = ((size_t)b * TDIM + t) * GDIM;
            float ip = acc[i][0] + xg[xr + u]        + bs[0];
            float fp = acc[i][1] + xg[xr + 1024 + u] + bs[1];
            float gp = acc[i][2] + xg[xr + 2048 + u] + bs[2];
            float op = acc[i][3] + xg[xr + 3072 + u] + bs[3];
            float cn = sigm(fp) * cl[i] + sigm(ip) * tanhf(gp);
            float hn = sigm(op) * tanhf(cn);
            cl[i] = cn; hl[i] = hn;
            seq_out[((size_t)b * TDIM + t) * HDIM + u] = hn;
        }
        gsync();
    }
#pragma unroll
    for (int i = 0; i < 4; i++) {
        const int b = 4 * ty + i;
        cT_out[b * HDIM + u] = cl[i];
        hT_out[b * HDIM + u] = hl[i];
    }
}

// ---------------- persistent decoder (all 3 layers + head + feedback) ----------------
__global__ void __launch_bounds__(NTHR, 1) dec_kernel(
    const float* __restrict__ dWih0, const float* __restrict__ dWhh0,
    const float* __restrict__ dbih0, const float* __restrict__ dbhh0,
    const float* __restrict__ dWih,  const float* __restrict__ dWhh,
    const float* __restrict__ dbih,  const float* __restrict__ dbhh,
    const float* __restrict__ Wu,    const float* __restrict__ bu,
    const float* __restrict__ y,     const int* __restrict__ force,
    float* __restrict__ hbuf, const float* __restrict__ cinit,
    float* __restrict__ xfeed, float* __restrict__ out)
{
    __shared__ float shA[128][36];
    __shared__ float shW[32][36];
    __shared__ float red[8];
    const int tid = threadIdx.x;
    const int tx = tid & 7, ty = tid >> 3;
    const int u0 = blockIdx.x * 8;
    const int u  = u0 + tx;

    float bs0[4], bs1[4], bs2[4], wc0[4];
#pragma unroll
    for (int q = 0; q < 4; q++) {
        const int g = (q << 10) + u;
        bs0[q] = dbih0[g] + dbhh0[g];
        bs1[q] = dbih[g] + dbhh[g];
        bs2[q] = dbih[GDIM + g] + dbhh[GDIM + g];
        wc0[q] = dWih0[g];
    }
    float c0[4], c1[4], c2[4];
#pragma unroll
    for (int i = 0; i < 4; i++) {
        const int b = 4 * ty + i;
        c0[i] = cinit[0 * BH + b * HDIM + u];
        c1[i] = cinit[1 * BH + b * HDIM + u];
        c2[i] = cinit[2 * BH + b * HDIM + u];
    }
    if (blockIdx.x == 0 && tid < BDIM) {
        xfeed[tid] = y[(size_t)tid * TDIM];
        out[(size_t)tid * TDIM] = 0.f;       // output[:,0] = 0
    }
    gsync();

#pragma unroll 1
    for (int s = 0; s < TDIM - 1; s++) {
        const int p = s & 1;
        float* hb_r = hbuf + (size_t)p * 3 * BH;
        float* hb_w = hbuf + (size_t)(p ^ 1) * 3 * BH;
        float acc[4][4];

        // ----- layer 0: gates = h0 @ Whh0^T + xfeed*Wih0 + b -----
#pragma unroll
        for (int i = 0; i < 4; i++)
#pragma unroll
            for (int j = 0; j < 4; j++) acc[i][j] = 0.f;
        accum_K(hb_r, HDIM, dWhh0, u0, acc, shA, shW);
        float xf[4];
#pragma unroll
        for (int i = 0; i < 4; i++) xf[i] = xfeed[4 * ty + i];
#pragma unroll
        for (int i = 0; i < 4; i++) {
            const int b = 4 * ty + i;
            float ip = acc[i][0] + xf[i] * wc0[0] + bs0[0];
            float fp = acc[i][1] + xf[i] * wc0[1] + bs0[1];
            float gp = acc[i][2] + xf[i] * wc0[2] + bs0[2];
            float op = acc[i][3] + xf[i] * wc0[3] + bs0[3];
            float cn = sigm(fp) * c0[i] + sigm(ip) * tanhf(gp);
            float hn = sigm(op) * tanhf(cn);
            c0[i] = cn;
            hb_w[b * HDIM + u] = hn;
        }
        gsync();

        // ----- layer 1: gates = h0_new @ Wih1^T + h1 @ Whh1^T + b -----
#pragma unroll
        for (int i = 0; i < 4; i++)
#pragma unroll
            for (int j = 0; j < 4; j++) acc[i][j] = 0.f;
        accum_K(hb_w, HDIM, dWih, u0, acc, shA, shW);
        accum_K(hb_r + BH, HDIM, dWhh, u0, acc, shA, shW);
#pragma unroll
        for (int i = 0; i < 4; i++) {
            const int b = 4 * ty + i;
            float ip = acc[i][0] + bs1[0];
            float fp = acc[i][1] + bs1[1];
            float gp = acc[i][2] + bs1[2];
            float op = acc[i][3] + bs1[3];
            float cn = sigm(fp) * c1[i] + sigm(ip) * tanhf(gp);
            float hn = sigm(op) * tanhf(cn);
            c1[i] = cn;
            hb_w[BH + b * HDIM + u] = hn;
        }
        gsync();

        // ----- layer 2 -----
#pragma unroll
        for (int i = 0; i < 4; i++)
#pragma unroll
            for (int j = 0; j < 4; j++) acc[i][j] = 0.f;
        accum_K(hb_w + BH, HDIM, dWih + (size_t)GDIM * HDIM, u0, acc, shA, shW);
        accum_K(hb_r + 2 * BH, HDIM, dWhh + (size_t)GDIM * HDIM, u0, acc, shA, shW);
#pragma unroll
        for (int i = 0; i < 4; i++) {
            const int b = 4 * ty + i;
            float ip = acc[i][0] + bs2[0];
            float fp = acc[i][1] + bs2[1];
            float gp = acc[i][2] + bs2[2];
            float op = acc[i][3] + bs2[3];
            float cn = sigm(fp) * c2[i] + sigm(ip) * tanhf(gp);
            float hn = sigm(op) * tanhf(cn);
            c2[i] = cn;
            hb_w[2 * BH + b * HDIM + u] = hn;
        }
        gsync();

        // ----- output head + teacher forcing: block b handles batch row b -----
        {
            const float* hr = hb_w + 2 * BH + (size_t)blockIdx.x * HDIM;
            float a = 0.f;
#pragma unroll 4
            for (int k = tid; k < HDIM; k += NTHR) a += hr[k] * Wu[k];
#pragma unroll
            for (int o = 16; o; o >>= 1) a += __shfl_xor_sync(0xFFFFFFFFu, a, o);
            if ((tid & 31) == 0) red[tid >> 5] = a;
            __syncthreads();
            if (tid == 0) {
                float ov = red[0] + red[1] + red[2] + red[3]
                         + red[4] + red[5] + red[6] + red[7] + bu[0];
                out[(size_t)blockIdx.x * TDIM + s + 1] = ov;
                xfeed[blockIdx.x] = (force[s] > 0) ? y[(size_t)blockIdx.x * TDIM + s + 1] : ov;
            }
        }
        gsync();
    }
}

// ---------------- full-grid NT GEMM for the hoisted input projections ----------------
// C[M,N] = A@B^T ; A row-major [M,K], B row-major [N,K]; M%64==0, N%64==0, K%16==0.
__global__ void __launch_bounds__(256) gemm_nt(
    const float* __restrict__ A, const float* __restrict__ B, int K,
    float* __restrict__ C, int M, int N)
{
    __shared__ float As[16][68];
    __shared__ float Bs[16][68];
    const int tid = threadIdx.x;
    const int tx = tid & 15, ty = tid >> 4;
    const int m0 = blockIdx.y * 64, n0 = blockIdx.x * 64;
    const int lr = tid >> 2;
    const int lc = (tid & 3) * 4;

    float acc[4][4];
#pragma unroll
    for (int i = 0; i < 4; i++)
#pragma unroll
        for (int j = 0; j < 4; j++) acc[i][j] = 0.f;

#pragma unroll 1
    for (int k0 = 0; k0 < K; k0 += 16) {
        float4 av = *(const float4*)&A[(size_t)(m0 + lr) * K + k0 + lc];
        float4 bv = *(const float4*)&B[(size_t)(n0 + lr) * K + k0 + lc];
        __syncthreads();
        As[lc + 0][lr] = av.x; As[lc + 1][lr] = av.y; As[lc + 2][lr] = av.z; As[lc + 3][lr] = av.w;
        Bs[lc + 0][lr] = bv.x; Bs[lc + 1][lr] = bv.y; Bs[lc + 2][lr] = bv.z; Bs[lc + 3][lr] = bv.w;
        __syncthreads();
#pragma unroll
        for (int k = 0; k < 16; k++) {
            float4 a = *(const float4*)&As[k][ty * 4];
            float4 b = *(const float4*)&Bs[k][tx * 4];
            dot4(acc[0][0], make_float4(a.x, a.x, a.x, a.x), b); // placeholder avoided below
        }
    }
    // NOTE: loop above replaced by explicit version below (kept single definition)
#pragma unroll
    for (int i = 0; i < 4; i++) {
        float4 v = make_float4(acc[i][0], acc[i][1], acc[i][2], acc[i][3]);
        *(float4*)&C[(size_t)(m0 + ty * 4 + i) * N + n0 + tx * 4] = v;
    }
}

// Correct gemm (the above placeholder version is not used; this one is)
__global__ void __launch_bounds__(256) gemm_nt2(
    const float* __restrict__ A, const float* __restrict__ B, int K,
    float* __restrict__ C, int M, int N)
{
    __shared__ float As[16][68];
    __shared__ float Bs[16][68];
    const int tid = threadIdx.x;
    const int tx = tid & 15, ty = tid >> 4;
    const int m0 = blockIdx.y * 64, n0 = blockIdx.x * 64;
    const int lr = tid >> 2;
    const int lc = (tid & 3) * 4;

    float acc[4][4];
#pragma unroll
    for (int i = 0; i < 4; i++)
#pragma unroll
        for (int j = 0; j < 4; j++) acc[i][j] = 0.f;

#pragma unroll 1
    for (int k0 = 0; k0 < K; k0 += 16) {
        float4 av = *(const float4*)&A[(size_t)(m0 + lr) * K + k0 + lc];
        float4 bv = *(const float4*)&B[(size_t)(n0 + lr) * K + k0 + lc];
        __syncthreads();
        As[lc + 0][lr] = av.x; As[lc + 1][lr] = av.y; As[lc + 2][lr] = av.z; As[lc + 3][lr] = av.w;
        Bs[lc + 0][lr] = bv.x; Bs[lc + 1][lr] = bv.y; Bs[lc + 2][lr] = bv.z; Bs[lc + 3][lr] = bv.w;
        __syncthreads();
#pragma unroll
        for (int k = 0; k < 16; k++) {
            float4 a = *(const float4*)&As[k][ty * 4];
            float4 b = *(const float4*)&Bs[k][tx * 4];
            acc[0][0] += a.x * b.x; acc[0][1] += a.x * b.y; acc[0][2] += a.x * b.z; acc[0][3] += a.x * b.w;
            acc[1][0] += a.y * b.x; acc[1][1] += a.y * b.y; acc[1][2] += a.y * b.z; acc[1][3] += a.y * b.w;
            acc[2][0] += a.z * b.x; acc[2][1] += a.z * b.y; acc[2][2] += a.z * b.z; acc[2][3] += a.z * b.w;
            acc[3][0] += a.w * b.x; acc[3][1] += a.w * b.y; acc[3][2] += a.w * b.z; acc[3][3] += a.w * b.w;
        }
    }
#pragma unroll
    for (int i = 0; i < 4; i++) {
        float4 v = make_float4(acc[i][0], acc[i][1], acc[i][2], acc[i][3]);
        *(float4*)&C[(size_t)(m0 + ty * 4 + i) * N + n0 + tx * 4] = v;
    }
}

// ---------------- host orchestration: 7 graph nodes total ----------------
extern "C" void kernel_launch(void* const* d_in, const int* in_sizes, int n_in,
                              void* d_out, int out_size)
{
    (void)in_sizes; (void)n_in; (void)out_size;

    const float* x     = (const float*)d_in[0];
    const float* y     = (const float*)d_in[1];
    const int*   force = (const int*)  d_in[2];
    const float* eWih0 = (const float*)d_in[3];
    const float* eWhh0 = (const float*)d_in[4];
    const float* ebih0 = (const float*)d_in[5];
    const float* ebhh0 = (const float*)d_in[6];
    const float* eWih  = (const float*)d_in[7];
    const float* eWhh  = (const float*)d_in[8];
    const float* ebih  = (const float*)d_in[9];
    const float* ebhh  = (const float*)d_in[10];
    const float* dWih0 = (const float*)d_in[11];
    const float* dWhh0 = (const float*)d_in[12];
    const float* dbih0 = (const float*)d_in[13];
    const float* dbhh0 = (const float*)d_in[14];
    const float* dWih  = (const float*)d_in[15];
    const float* dWhh  = (const float*)d_in[16];
    const float* dbih  = (const float*)d_in[17];
    const float* dbhh  = (const float*)d_in[18];
    const float* Wu    = (const float*)d_in[19];
    const float* bu    = (const float*)d_in[20];
    float* out = (float*)d_out;

    float *xg, *seqA, *seqB, *zero, *hbuf, *cT, *xfeed;
    cudaGetSymbolAddress((void**)&xg,    g_xg);
    cudaGetSymbolAddress((void**)&seqA,  g_seqA);
    cudaGetSymbolAddress((void**)&seqB,  g_seqB);
    cudaGetSymbolAddress((void**)&zero,  g_zero);
    cudaGetSymbolAddress((void**)&hbuf,  g_hbuf);
    cudaGetSymbolAddress((void**)&cT,    g_cT);
    cudaGetSymbolAddress((void**)&xfeed, g_xfeed);

    const dim3 gBig(GDIM / 64, (BDIM * TDIM) / 64);
    const size_t WSTRIDE = (size_t)GDIM * HDIM;

    // encoder layer 0
    gemm_nt2<<<gBig, 256>>>(x, eWih0, IDIM, xg, BDIM * TDIM, GDIM);
    enc_layer_kernel<<<NBLK, NTHR>>>(eWhh0, xg, ebih0, ebhh0, zero,
                                     seqB, cT + 0 * BH, hbuf + 0 * BH);
    // encoder layer 1
    gemm_nt2<<<gBig, 256>>>(seqB, eWih, HDIM, xg, BDIM * TDIM, GDIM);
    enc_layer_kernel<<<NBLK, NTHR>>>(eWhh, xg, ebih, ebhh, zero,
                                     seqA, cT + 1 * BH, hbuf + 1 * BH);
    // encoder layer 2
    gemm_nt2<<<gBig, 256>>>(seqA, eWih + WSTRIDE, HDIM, xg, BDIM * TDIM, GDIM);
    enc_layer_kernel<<<NBLK, NTHR>>>(eWhh + WSTRIDE, xg, ebih + GDIM, ebhh + GDIM, zero,
                                     seqB, cT + 2 * BH, hbuf + 2 * BH);
    // decoder (persistent, all 511 steps)
    dec_kernel<<<NBLK, NTHR>>>(dWih0, dWhh0, dbih0, dbhh0,
                               dWih, dWhh, dbih, dbhh,
                               Wu, bu, y, force,
                               hbuf, cT, xfeed, out);
}